// round 4
// baseline (speedup 1.0000x reference)
#include <cuda_runtime.h>

#define NN 12288
#define BB 32
#define KSTEP 32
#define TILE_M 128
#define NTILES (NN / TILE_M)   // 96
#define LCHUNK 6               // K-chunks for shared layers (12288/6 = 2048)
#define RCHUNK 2               // K-chunks for retina       (1024/2  = 512)

typedef unsigned long long u64;

// ------------------- device scratch (no allocations allowed) -------------------
__device__ float g_xT[1024 * BB];                 // x transposed [r][b]
__device__ float g_actA[NN * BB];                 // activations [n][b]
__device__ float g_actB[NN * BB];
__device__ float g_part[(size_t)LCHUNK * NN * BB];// K-chunk partials
__device__ float g_fin[64 * NN];                  // [j][m] final contributions

__device__ __forceinline__ float* buf_ptr(int s) {
    return (s == 0) ? g_xT : ((s == 1) ? g_actA : g_actB);
}

union UF2 { u64 u; float2 f; };

__device__ __forceinline__ void fma2(u64& acc, u64 a, u64 b) {
    asm("fma.rn.f32x2 %0, %1, %2, %0;" : "+l"(acc) : "l"(a), "l"(b));
}

// ------------------- x[32][1024] -> xT[1024][32] -------------------
__global__ void transpose_x_kernel(const float* __restrict__ x) {
    int i = blockIdx.x * blockDim.x + threadIdx.x;   // 32768
    int b = i >> 10, r = i & 1023;
    g_xT[r * BB + b] = x[i];
}

// ------------------- main layer kernel -------------------
// out[m][b] = sum_k W[m][k] * in[k][b]  for one (row-tile, K-chunk).
// 128 threads, thread tile: 8 rows x 4 batches, f32x2 accumulators (row pairs).
__global__ __launch_bounds__(128, 4)
void layer_kernel(const float* __restrict__ W, int in_sel, int K, int nchunks)
{
    __shared__ __align__(16) float sWt[2][KSTEP * TILE_M]; // transposed W, swizzled (32KB)
    __shared__ __align__(16) u64   sAs[2][KSTEP * BB];     // act splats, rotated   (16KB)

    const float* in = buf_ptr(in_sel);

    const int tid  = threadIdx.x;
    const int lane = tid & 31;
    const int wid  = tid >> 5;        // 0..3
    const int bg   = lane & 7;        // batch group: 4 batches
    const int rg   = lane >> 3;       // 0..3
    const int bg4  = bg * 4;

    const int tile = blockIdx.x / nchunks;
    const int kc   = blockIdx.x % nchunks;
    const int klen = K / nchunks;
    const int k0   = kc * klen;
    const int mbase = tile * TILE_M;
    float* out = g_part + (size_t)kc * (NN * BB);

    const int wrow = wid * 32 + rg * 8;   // this thread's 8 rows (within tile)

    // staging roles
    const int q      = tid & 3;          // 4 threads per row / per act-col
    const int rowloc = tid >> 2;         // 0..31
    const int ca     = tid >> 2;         // act column handled by this thread
    const int arot   = (ca & 7) * 4;

    u64 acc[4][4];
    #pragma unroll
    for (int i = 0; i < 4; i++)
        #pragma unroll
        for (int j = 0; j < 4; j++) acc[i][j] = 0ull;

    const int steps = klen / KSTEP;

    float pwf[32];   // staged W values (held across compute)
    float paf[8];    // staged act values

    // ---- stage step 0 directly ----
    {
        const int kk = k0;
        #pragma unroll
        for (int p = 0; p < 4; p++) {
            const float* g = W + (size_t)(mbase + p * 32 + rowloc) * K + kk + q * 8;
            float4 v0 = *(const float4*)(g);
            float4 v1 = *(const float4*)(g + 4);
            pwf[p*8+0]=v0.x; pwf[p*8+1]=v0.y; pwf[p*8+2]=v0.z; pwf[p*8+3]=v0.w;
            pwf[p*8+4]=v1.x; pwf[p*8+5]=v1.y; pwf[p*8+6]=v1.z; pwf[p*8+7]=v1.w;
        }
        {
            const float* g = in + (size_t)(kk + ca) * BB + q * 8;
            float4 v0 = *(const float4*)(g);
            float4 v1 = *(const float4*)(g + 4);
            paf[0]=v0.x; paf[1]=v0.y; paf[2]=v0.z; paf[3]=v0.w;
            paf[4]=v1.x; paf[5]=v1.y; paf[6]=v1.z; paf[7]=v1.w;
        }
        #pragma unroll
        for (int p = 0; p < 4; p++) {
            int row = p * 32 + rowloc;
            int wrx = row ^ (q * 8);
            #pragma unroll
            for (int j = 0; j < 8; j++) {
                int c = q * 8 + j;
                sWt[0][c * TILE_M + wrx] = pwf[p*8+j];
            }
        }
        #pragma unroll
        for (int j = 0; j < 8; j++) {
            int b = q * 8 + j;
            UF2 v; v.f = make_float2(paf[j], paf[j]);
            sAs[0][ca * BB + ((b + arot) & 31)] = v.u;
        }
    }
    __syncthreads();

    #pragma unroll 1
    for (int s = 0; s < steps; s++) {
        const int buf = s & 1;
        const bool more = (s + 1) < steps;

        if (more) {
            const int kk = k0 + (s + 1) * KSTEP;
            #pragma unroll
            for (int p = 0; p < 4; p++) {
                const float* g = W + (size_t)(mbase + p * 32 + rowloc) * K + kk + q * 8;
                float4 v0 = *(const float4*)(g);
                float4 v1 = *(const float4*)(g + 4);
                pwf[p*8+0]=v0.x; pwf[p*8+1]=v0.y; pwf[p*8+2]=v0.z; pwf[p*8+3]=v0.w;
                pwf[p*8+4]=v1.x; pwf[p*8+5]=v1.y; pwf[p*8+6]=v1.z; pwf[p*8+7]=v1.w;
            }
            const float* g = in + (size_t)(kk + ca) * BB + q * 8;
            float4 v0 = *(const float4*)(g);
            float4 v1 = *(const float4*)(g + 4);
            paf[0]=v0.x; paf[1]=v0.y; paf[2]=v0.z; paf[3]=v0.w;
            paf[4]=v1.x; paf[5]=v1.y; paf[6]=v1.z; paf[7]=v1.w;
        }

        // ---- compute 32 k's from buf ----
        const float* wtb = sWt[buf];
        const u64*   asb = sAs[buf];
        #pragma unroll 1
        for (int cc = 0; cc < 4; cc++) {
            const int wmx = wrow ^ (cc * 8);
            #pragma unroll
            for (int u = 0; u < 8; u++) {
                const int c = cc * 8 + u;
                const float* wp = wtb + c * TILE_M + wmx;
                ulonglong2 wA = *(const ulonglong2*)(wp);
                ulonglong2 wB = *(const ulonglong2*)(wp + 4);
                const int b0 = (bg4 + u * 4) & 31;
                const u64* ap = asb + c * BB + b0;
                ulonglong2 aA = *(const ulonglong2*)(ap);
                ulonglong2 aB = *(const ulonglong2*)(ap + 2);
                fma2(acc[0][0], wA.x, aA.x); fma2(acc[0][1], wA.x, aA.y);
                fma2(acc[0][2], wA.x, aB.x); fma2(acc[0][3], wA.x, aB.y);
                fma2(acc[1][0], wA.y, aA.x); fma2(acc[1][1], wA.y, aA.y);
                fma2(acc[1][2], wA.y, aB.x); fma2(acc[1][3], wA.y, aB.y);
                fma2(acc[2][0], wB.x, aA.x); fma2(acc[2][1], wB.x, aA.y);
                fma2(acc[2][2], wB.x, aB.x); fma2(acc[2][3], wB.x, aB.y);
                fma2(acc[3][0], wB.y, aA.x); fma2(acc[3][1], wB.y, aA.y);
                fma2(acc[3][2], wB.y, aB.x); fma2(acc[3][3], wB.y, aB.y);
            }
        }

        // ---- store staged regs into other buffer ----
        if (more) {
            const int nb = buf ^ 1;
            #pragma unroll
            for (int p = 0; p < 4; p++) {
                int row = p * 32 + rowloc;
                int wrx = row ^ (q * 8);
                #pragma unroll
                for (int j = 0; j < 8; j++) {
                    int c = q * 8 + j;
                    sWt[nb][c * TILE_M + wrx] = pwf[p*8+j];
                }
            }
            #pragma unroll
            for (int j = 0; j < 8; j++) {
                int b = q * 8 + j;
                UF2 v; v.f = make_float2(paf[j], paf[j]);
                sAs[nb][ca * BB + ((b + arot) & 31)] = v.u;
            }
        }
        __syncthreads();
    }

    // ---- epilogue: rows wrow+2rp (lo) and wrow+2rp+1 (hi), batches bg4..bg4+3 ----
    #pragma unroll
    for (int rp = 0; rp < 4; rp++) {
        UF2 a0, a1, a2, a3;
        a0.u = acc[rp][0]; a1.u = acc[rp][1]; a2.u = acc[rp][2]; a3.u = acc[rp][3];
        float4 vlo = make_float4(a0.f.x, a1.f.x, a2.f.x, a3.f.x);
        float4 vhi = make_float4(a0.f.y, a1.f.y, a2.f.y, a3.f.y);
        float* r0 = out + (size_t)(mbase + wrow + 2 * rp) * BB;
        float* r1 = out + (size_t)(mbase + wrow + 2 * rp + 1) * BB;
        ((float4*)r0)[bg] = vlo;
        ((float4*)r1)[bg] = vhi;
    }
}

// ------------------- sum K-chunk partials -> activation buffer -------------------
__global__ void reduce_kernel(int dst_sel, int nslabs) {
    int i = blockIdx.x * blockDim.x + threadIdx.x;   // < 98304 float4s
    const int Q = NN * BB / 4;
    if (i >= Q) return;
    const float4* p = (const float4*)g_part;
    float4 s = p[i];
    for (int c = 1; c < nslabs; c++) {
        float4 v = p[i + (size_t)c * Q];
        s.x += v.x; s.y += v.y; s.z += v.z; s.w += v.w;
    }
    ((float4*)buf_ptr(dst_sel))[i] = s;
}

// ------------------- fused layer-4 + rational readout -------------------
// One warp per shared-layer output row m; only rows with nonzero W_rational
// columns (~64 of 12288) do the dot product. Deterministic scratch output.
__global__ __launch_bounds__(256)
void final_kernel(const float* __restrict__ Wsh, const float* __restrict__ Wr,
                  int act_sel)
{
    __shared__ float red[8][32][33];
    const float* act = buf_ptr(act_sel);

    int tid = threadIdx.x, lane = tid & 31, w = tid >> 5;
    int m = blockIdx.x * 8 + w;

    float w0 = Wr[m];
    float w1 = Wr[NN + m];

    if (w0 == 0.0f && w1 == 0.0f) {
        g_fin[(size_t)(lane * 2 + 0) * NN + m] = 0.0f;
        g_fin[(size_t)(lane * 2 + 1) * NN + m] = 0.0f;
        return;
    }

    float acc[32];
    #pragma unroll
    for (int b = 0; b < 32; b++) acc[b] = 0.0f;

    const float4* a4 = (const float4*)act;
    const float* wrowp = Wsh + (size_t)m * NN;

    for (int k = lane; k < NN; k += 32) {
        float wv = wrowp[k];
        #pragma unroll
        for (int j = 0; j < 8; j++) {
            float4 av = a4[(size_t)k * 8 + j];
            acc[4*j+0] += wv * av.x;
            acc[4*j+1] += wv * av.y;
            acc[4*j+2] += wv * av.z;
            acc[4*j+3] += wv * av.w;
        }
    }

    #pragma unroll
    for (int b = 0; b < 32; b++) red[w][lane][b] = acc[b];
    __syncwarp();

    float y = 0.0f;
    #pragma unroll
    for (int i = 0; i < 32; i++) y += red[w][i][lane];

    g_fin[(size_t)(lane * 2 + 0) * NN + m] = w0 * y;
    g_fin[(size_t)(lane * 2 + 1) * NN + m] = w1 * y;
}

// ------------------- deterministic reduction of g_fin -> out[64] -------------------
__global__ void final_reduce_kernel(float* __restrict__ out) {
    __shared__ float s[256];
    int j = blockIdx.x;           // 0..63 -> out[b*2+o]
    float v = 0.0f;
    for (int m = threadIdx.x; m < NN; m += 256) v += g_fin[(size_t)j * NN + m];
    s[threadIdx.x] = v;
    __syncthreads();
    for (int off = 128; off > 0; off >>= 1) {
        if (threadIdx.x < off) s[threadIdx.x] += s[threadIdx.x + off];
        __syncthreads();
    }
    if (threadIdx.x == 0) out[j] = s[0];
}

// ------------------- launch -------------------
extern "C" void kernel_launch(void* const* d_in, const int* in_sizes, int n_in,
                              void* d_out, int out_size) {
    const float* x    = (const float*)d_in[0];
    const float* Wret = (const float*)d_in[1];
    const float* Wsh  = (const float*)d_in[2];
    const float* Wrat = (const float*)d_in[3];
    float* out = (float*)d_out;

    transpose_x_kernel<<<128, 256>>>(x);

    // retina: K=1024, 2 chunks  -> g_actA
    layer_kernel<<<NTILES * RCHUNK, 128>>>(Wret, 0, 1024, RCHUNK);
    reduce_kernel<<<384, 256>>>(1, RCHUNK);

    // shared layer 1: g_actA -> g_actB
    layer_kernel<<<NTILES * LCHUNK, 128>>>(Wsh, 1, NN, LCHUNK);
    reduce_kernel<<<384, 256>>>(2, LCHUNK);

    // shared layer 2: g_actB -> g_actA
    layer_kernel<<<NTILES * LCHUNK, 128>>>(Wsh, 2, NN, LCHUNK);
    reduce_kernel<<<384, 256>>>(1, LCHUNK);

    // shared layer 3: g_actA -> g_actB
    layer_kernel<<<NTILES * LCHUNK, 128>>>(Wsh, 1, NN, LCHUNK);
    reduce_kernel<<<384, 256>>>(2, LCHUNK);

    // fused shared layer 4 + rational readout
    final_kernel<<<NN / 8, 256>>>(Wsh, Wrat, 2);
    final_reduce_kernel<<<64, 256>>>(out);
}

// round 6
// speedup vs baseline: 3.1735x; 3.1735x over previous
#include <cuda_runtime.h>
#include <cstdint>

#define NN 12288
#define BB 32
#define RR 1024
#define STRIDE 1024            // padded nz slots per row (mean 614, +16 sigma safe)

typedef unsigned long long u64;

// ------------------- device scratch (no allocations allowed) -------------------
__device__ float g_xT[RR * BB];                 // x transposed [r][b]
__device__ float g_actA[NN * BB];               // activations [n][b]
__device__ float g_actB[NN * BB];
__device__ float g_fin[64 * NN];                // [j][m] final contributions
__device__ u64   g_nz[(size_t)NN * STRIDE];     // packed {val(hi32), col(lo32)}
__device__ unsigned int g_cnt[NN];              // padded nz count per row (mult of 32)

__device__ __forceinline__ float* buf_ptr(int s) {
    return (s == 1) ? g_actA : g_actB;
}

// ------------------- x[32][1024] -> xT[1024][32] -------------------
__global__ void transpose_x_kernel(const float* __restrict__ x) {
    int i = blockIdx.x * blockDim.x + threadIdx.x;   // 32768
    int b = i >> 10, r = i & 1023;
    g_xT[r * BB + b] = x[i];
}

// ------------------- CSR build: warp-per-row stream compaction -------------------
// Deterministic order (r, j, lane). Pads each row to a multiple of 32 with zeros.
__global__ __launch_bounds__(256)
void build_kernel(const float* __restrict__ W) {
    const int m    = blockIdx.x * 8 + (threadIdx.x >> 5);
    const int lane = threadIdx.x & 31;
    const float4* row4 = (const float4*)(W + (size_t)m * NN);
    u64* out = g_nz + (size_t)m * STRIDE;

    unsigned int base = 0;
    for (int r = 0; r < NN / 128; r++) {
        float4 v = row4[r * 32 + lane];
        const int k0 = r * 128 + lane * 4;
        float vv[4] = {v.x, v.y, v.z, v.w};
        #pragma unroll
        for (int j = 0; j < 4; j++) {
            float xv = vv[j];
            unsigned mask = __ballot_sync(0xffffffffu, xv != 0.0f);
            if (xv != 0.0f) {
                unsigned pos = base + __popc(mask & ((1u << lane) - 1u));
                if (pos < STRIDE) {
                    u64 e = (((u64)__float_as_uint(xv)) << 32) | (u64)(unsigned)(k0 + j);
                    out[pos] = e;
                }
            }
            base += __popc(mask);
        }
    }
    unsigned int cnt = base < STRIDE ? base : STRIDE;
    unsigned int padded = (cnt + 31u) & ~31u;
    if (padded > STRIDE) padded = STRIDE;
    for (unsigned int p = cnt + lane; p < padded; p += 32) out[p] = 0ull;
    if (lane == 0) g_cnt[m] = padded;
}

// ------------------- retina: warp-per-row dense, zero-row skip -------------------
// out[m][b] = sum_r Wret[m][r] * xT[r][b]; inactive rows (mask=0) are all-zero.
__global__ __launch_bounds__(256)
void retina_kernel(const float* __restrict__ Wret) {
    __shared__ float sw[8][32];
    const int wslot = threadIdx.x >> 5;
    const int lane  = threadIdx.x & 31;
    const int m = blockIdx.x * 8 + wslot;
    const float* row = Wret + (size_t)m * RR;

    // A masked (inactive) row is exactly zero everywhere; an active row is
    // Gaussian and has ~zero probability of 32 leading exact zeros.
    float probe = row[lane];
    if (__ballot_sync(0xffffffffu, probe != 0.0f) == 0u) {
        g_actA[m * BB + lane] = 0.0f;
        return;
    }

    float acc = 0.0f;
    for (int c = 0; c < RR; c += 32) {
        sw[wslot][lane] = row[c + lane];
        __syncwarp();
        #pragma unroll 8
        for (int j = 0; j < 32; j++)
            acc += sw[wslot][j] * g_xT[(c + j) * BB + lane];
        __syncwarp();
    }
    g_actA[m * BB + lane] = acc;
}

// ------------------- sparse layer: out[m][b] = sum_nz val * act[col][b] -------------------
__global__ __launch_bounds__(256, 8)
void spmm_kernel(int in_sel, int out_sel) {
    __shared__ u64 sh[8][32];
    const int wslot = threadIdx.x >> 5;
    const int lane  = threadIdx.x & 31;
    const int m = blockIdx.x * 8 + wslot;

    const float* act = buf_ptr(in_sel);
    const u64* nz = g_nz + (size_t)m * STRIDE;
    const unsigned int cnt = g_cnt[m];   // multiple of 32

    float acc = 0.0f;
    for (unsigned int c = 0; c < cnt; c += 32) {
        sh[wslot][lane] = nz[c + lane];
        __syncwarp();
        #pragma unroll 8
        for (int j = 0; j < 32; j++) {
            u64 e = sh[wslot][j];
            unsigned col = (unsigned)e;
            float val = __uint_as_float((unsigned)(e >> 32));
            acc += val * act[col * BB + lane];
        }
        __syncwarp();
    }
    buf_ptr(out_sel)[m * BB + lane] = acc;
}

// ------------------- fused layer-4 + rational readout (CSR reuse) -------------------
__global__ __launch_bounds__(256)
void final_kernel(const float* __restrict__ Wr, int act_sel) {
    __shared__ u64 sh[8][32];
    const int wslot = threadIdx.x >> 5;
    const int lane  = threadIdx.x & 31;
    const int m = blockIdx.x * 8 + wslot;

    float w0 = Wr[m];
    float w1 = Wr[NN + m];

    if (w0 == 0.0f && w1 == 0.0f) {
        g_fin[(size_t)(lane * 2 + 0) * NN + m] = 0.0f;
        g_fin[(size_t)(lane * 2 + 1) * NN + m] = 0.0f;
        return;
    }

    const float* act = buf_ptr(act_sel);
    const u64* nz = g_nz + (size_t)m * STRIDE;
    const unsigned int cnt = g_cnt[m];

    float acc = 0.0f;
    for (unsigned int c = 0; c < cnt; c += 32) {
        sh[wslot][lane] = nz[c + lane];
        __syncwarp();
        #pragma unroll 8
        for (int j = 0; j < 32; j++) {
            u64 e = sh[wslot][j];
            unsigned col = (unsigned)e;
            float val = __uint_as_float((unsigned)(e >> 32));
            acc += val * act[col * BB + lane];
        }
        __syncwarp();
    }

    g_fin[(size_t)(lane * 2 + 0) * NN + m] = w0 * acc;
    g_fin[(size_t)(lane * 2 + 1) * NN + m] = w1 * acc;
}

// ------------------- deterministic reduction of g_fin -> out[64] -------------------
__global__ void final_reduce_kernel(float* __restrict__ out) {
    __shared__ float s[256];
    int j = blockIdx.x;           // 0..63 -> out[b*2+o]
    float v = 0.0f;
    for (int m = threadIdx.x; m < NN; m += 256) v += g_fin[(size_t)j * NN + m];
    s[threadIdx.x] = v;
    __syncthreads();
    for (int off = 128; off > 0; off >>= 1) {
        if (threadIdx.x < off) s[threadIdx.x] += s[threadIdx.x + off];
        __syncthreads();
    }
    if (threadIdx.x == 0) out[j] = s[0];
}

// ------------------- launch -------------------
extern "C" void kernel_launch(void* const* d_in, const int* in_sizes, int n_in,
                              void* d_out, int out_size) {
    const float* x    = (const float*)d_in[0];
    const float* Wret = (const float*)d_in[1];
    const float* Wsh  = (const float*)d_in[2];
    const float* Wrat = (const float*)d_in[3];
    float* out = (float*)d_out;

    transpose_x_kernel<<<128, 256>>>(x);
    build_kernel<<<NN / 8, 256>>>(Wsh);
    retina_kernel<<<NN / 8, 256>>>(Wret);      // -> g_actA

    spmm_kernel<<<NN / 8, 256>>>(1, 2);        // layer 1: actA -> actB
    spmm_kernel<<<NN / 8, 256>>>(2, 1);        // layer 2: actB -> actA
    spmm_kernel<<<NN / 8, 256>>>(1, 2);        // layer 3: actA -> actB

    final_kernel<<<NN / 8, 256>>>(Wrat, 2);    // fused layer 4 + readout
    final_reduce_kernel<<<64, 256>>>(out);
}

// round 8
// speedup vs baseline: 3.3030x; 1.0408x over previous
#include <cuda_runtime.h>
#include <cstdint>

#define NN 12288
#define BB 32
#define RR 1024
#define STRIDE 1024            // padded nz slots per row (mean 614; huge margin)

typedef unsigned long long u64;

// ------------------- device scratch (no allocations allowed) -------------------
__device__ float g_xT[RR * BB];                 // x transposed [r][b]
__device__ float g_actA[NN * BB];               // activations [n][b]
__device__ float g_actB[NN * BB];
__device__ float g_fin[64 * NN];                // [j][m] final contributions
__device__ __align__(16) u64 g_nz[(size_t)NN * STRIDE];  // packed {val(hi32), col*128(lo32)}
__device__ unsigned int g_cnt[NN];              // padded nz count per row (mult of 64)

__device__ __forceinline__ float* buf_ptr(int s) {
    return (s == 1) ? g_actA : g_actB;
}

// ------------------- x[32][1024] -> xT[1024][32] -------------------
__global__ void transpose_x_kernel(const float* __restrict__ x) {
    int i = blockIdx.x * blockDim.x + threadIdx.x;   // 32768
    int b = i >> 10, r = i & 1023;
    g_xT[r * BB + b] = x[i];
}

// ------------------- CSR build: warp-per-row stream compaction -------------------
// Entry = {val bits (hi32), col*128 byte-offset (lo32)}. Rows padded to mult of 64.
__global__ __launch_bounds__(256)
void build_kernel(const float* __restrict__ W) {
    const int m    = blockIdx.x * 8 + (threadIdx.x >> 5);
    const int lane = threadIdx.x & 31;
    const float4* row4 = (const float4*)(W + (size_t)m * NN);
    u64* out = g_nz + (size_t)m * STRIDE;

    unsigned int base = 0;
    for (int r = 0; r < NN / 128; r++) {
        float4 v = row4[r * 32 + lane];
        const int k0 = r * 128 + lane * 4;
        float vv[4] = {v.x, v.y, v.z, v.w};
        unsigned msk[4];
        #pragma unroll
        for (int j = 0; j < 4; j++)
            msk[j] = __ballot_sync(0xffffffffu, vv[j] != 0.0f);
        #pragma unroll
        for (int j = 0; j < 4; j++) {
            if (vv[j] != 0.0f) {
                unsigned pos = base + __popc(msk[j] & ((1u << lane) - 1u));
                if (pos < STRIDE) {
                    u64 e = (((u64)__float_as_uint(vv[j])) << 32)
                          | (u64)(unsigned)((k0 + j) * 128);
                    out[pos] = e;
                }
            }
            base += __popc(msk[j]);
        }
    }
    unsigned int cnt = base < STRIDE ? base : STRIDE;
    unsigned int padded = (cnt + 63u) & ~63u;
    if (padded > STRIDE) padded = STRIDE;
    for (unsigned int p = cnt + lane; p < padded; p += 32) out[p] = 0ull;
    if (lane == 0) g_cnt[m] = padded;
}

// ------------------- retina: warp-per-row dense, zero-row skip -------------------
__global__ __launch_bounds__(256)
void retina_kernel(const float* __restrict__ Wret) {
    __shared__ float sw[8][32];
    const int wslot = threadIdx.x >> 5;
    const int lane  = threadIdx.x & 31;
    const int m = blockIdx.x * 8 + wslot;
    const float* row = Wret + (size_t)m * RR;

    float probe = row[lane];
    if (__ballot_sync(0xffffffffu, probe != 0.0f) == 0u) {
        g_actA[m * BB + lane] = 0.0f;
        return;
    }

    float acc = 0.0f;
    for (int c = 0; c < RR; c += 32) {
        sw[wslot][lane] = row[c + lane];
        __syncwarp();
        #pragma unroll 8
        for (int j = 0; j < 32; j++)
            acc += sw[wslot][j] * g_xT[(c + j) * BB + lane];
        __syncwarp();
    }
    g_actA[m * BB + lane] = acc;
}

// ------------------- sparse layer -------------------
// out[m][b] = sum_nz val * act[col][b]. 64-entry chunks, LDS.128 broadcast
// (2 entries/access), 4 accumulators, register-prefetched staging.
__global__ __launch_bounds__(256, 8)
void spmm_kernel(int in_sel, int out_sel) {
    __shared__ __align__(16) uint4 sh[8][32];   // 64 entries per warp chunk
    const int wslot = threadIdx.x >> 5;
    const int lane  = threadIdx.x & 31;
    const int m = blockIdx.x * 8 + wslot;

    const char* actb = (const char*)buf_ptr(in_sel) + lane * 4;
    const uint4* nz4 = (const uint4*)(g_nz + (size_t)m * STRIDE);
    const unsigned int cnt = g_cnt[m];          // multiple of 64
    const unsigned int nch = cnt >> 6;

    float a0 = 0.f, a1 = 0.f, a2 = 0.f, a3 = 0.f;

    if (nch) {
        uint4 nxt = nz4[lane];
        for (unsigned int c = 0; c < nch; c++) {
            sh[wslot][lane] = nxt;
            __syncwarp();
            if (c + 1 < nch) nxt = nz4[(c + 1) * 32 + lane];
            const uint4* pe = sh[wslot];
            #pragma unroll
            for (int j = 0; j < 32; j += 4) {
                uint4 e0 = pe[j + 0];
                uint4 e1 = pe[j + 1];
                uint4 e2 = pe[j + 2];
                uint4 e3 = pe[j + 3];
                a0 += __uint_as_float(e0.y) * *(const float*)(actb + e0.x);
                a1 += __uint_as_float(e0.w) * *(const float*)(actb + e0.z);
                a2 += __uint_as_float(e1.y) * *(const float*)(actb + e1.x);
                a3 += __uint_as_float(e1.w) * *(const float*)(actb + e1.z);
                a0 += __uint_as_float(e2.y) * *(const float*)(actb + e2.x);
                a1 += __uint_as_float(e2.w) * *(const float*)(actb + e2.z);
                a2 += __uint_as_float(e3.y) * *(const float*)(actb + e3.x);
                a3 += __uint_as_float(e3.w) * *(const float*)(actb + e3.z);
            }
            __syncwarp();
        }
    }
    buf_ptr(out_sel)[m * BB + lane] = (a0 + a1) + (a2 + a3);
}

// ------------------- fused layer-4 + rational readout (CSR reuse) -------------------
__global__ __launch_bounds__(256)
void final_kernel(const float* __restrict__ Wr, int act_sel) {
    __shared__ __align__(16) uint4 sh[8][32];
    const int wslot = threadIdx.x >> 5;
    const int lane  = threadIdx.x & 31;
    const int m = blockIdx.x * 8 + wslot;

    float w0 = Wr[m];
    float w1 = Wr[NN + m];

    if (w0 == 0.0f && w1 == 0.0f) {
        g_fin[(size_t)(lane * 2 + 0) * NN + m] = 0.0f;
        g_fin[(size_t)(lane * 2 + 1) * NN + m] = 0.0f;
        return;
    }

    const char* actb = (const char*)buf_ptr(act_sel) + lane * 4;
    const uint4* nz4 = (const uint4*)(g_nz + (size_t)m * STRIDE);
    const unsigned int cnt = g_cnt[m];
    const unsigned int nch = cnt >> 6;

    float a0 = 0.f, a1 = 0.f, a2 = 0.f, a3 = 0.f;
    for (unsigned int c = 0; c < nch; c++) {
        sh[wslot][lane] = nz4[c * 32 + lane];
        __syncwarp();
        const uint4* pe = sh[wslot];
        #pragma unroll
        for (int j = 0; j < 32; j += 4) {
            uint4 e0 = pe[j + 0];
            uint4 e1 = pe[j + 1];
            uint4 e2 = pe[j + 2];
            uint4 e3 = pe[j + 3];
            a0 += __uint_as_float(e0.y) * *(const float*)(actb + e0.x);
            a1 += __uint_as_float(e0.w) * *(const float*)(actb + e0.z);
            a2 += __uint_as_float(e1.y) * *(const float*)(actb + e1.x);
            a3 += __uint_as_float(e1.w) * *(const float*)(actb + e1.z);
            a0 += __uint_as_float(e2.y) * *(const float*)(actb + e2.x);
            a1 += __uint_as_float(e2.w) * *(const float*)(actb + e2.z);
            a2 += __uint_as_float(e3.y) * *(const float*)(actb + e3.x);
            a3 += __uint_as_float(e3.w) * *(const float*)(actb + e3.z);
        }
        __syncwarp();
    }
    float acc = (a0 + a1) + (a2 + a3);

    g_fin[(size_t)(lane * 2 + 0) * NN + m] = w0 * acc;
    g_fin[(size_t)(lane * 2 + 1) * NN + m] = w1 * acc;
}

// ------------------- deterministic reduction of g_fin -> out[64] -------------------
__global__ void final_reduce_kernel(float* __restrict__ out) {
    __shared__ float s[256];
    int j = blockIdx.x;           // 0..63 -> out[b*2+o]
    float v = 0.0f;
    for (int m = threadIdx.x; m < NN; m += 256) v += g_fin[(size_t)j * NN + m];
    s[threadIdx.x] = v;
    __syncthreads();
    for (int off = 128; off > 0; off >>= 1) {
        if (threadIdx.x < off) s[threadIdx.x] += s[threadIdx.x + off];
        __syncthreads();
    }
    if (threadIdx.x == 0) out[j] = s[0];
}

// ------------------- launch -------------------
extern "C" void kernel_launch(void* const* d_in, const int* in_sizes, int n_in,
                              void* d_out, int out_size) {
    const float* x    = (const float*)d_in[0];
    const float* Wret = (const float*)d_in[1];
    const float* Wsh  = (const float*)d_in[2];
    const float* Wrat = (const float*)d_in[3];
    float* out = (float*)d_out;

    transpose_x_kernel<<<128, 256>>>(x);
    build_kernel<<<NN / 8, 256>>>(Wsh);
    retina_kernel<<<NN / 8, 256>>>(Wret);      // -> g_actA

    spmm_kernel<<<NN / 8, 256>>>(1, 2);        // layer 1: actA -> actB
    spmm_kernel<<<NN / 8, 256>>>(2, 1);        // layer 2: actB -> actA
    spmm_kernel<<<NN / 8, 256>>>(1, 2);        // layer 3: actA -> actB

    final_kernel<<<NN / 8, 256>>>(Wrat, 2);    // fused layer 4 + readout
    final_reduce_kernel<<<64, 256>>>(out);
}